// round 14
// baseline (speedup 1.0000x reference)
#include <cuda_runtime.h>
#include <cuda_bf16.h>
#include <mma.h>
#include <math.h>

using namespace nvcuda;

// Problem constants (fixed dataset)
#define NN      100000          // nodes
#define EE      1600000         // edges (without self loops)
#define ETOT    (EE + NN)       // with self loops
#define FIN     512
#define H1C     64              // 8 heads * 8 channels
#define NH1     8
#define OUTC    40
#define NEG_SLOPE 0.2f
#define EPS_F   1e-16f

#define SCAN_B  1024
#define NB_SCAN ((NN + SCAN_B - 1) / SCAN_B)   // 98

// GEMM1 tiling (64x64x32, 128 threads, cp.async pipelined)
#define GBM 64
#define GBK 32
#define GBN 64
#define NTILE (FIN / GBK)                       // 16
#define A_LD 40                                 // bf16 per A smem row (pad 8)
#define B_LD 72                                 // bf16 per B smem row (pad 8)
#define NROUND (((NN + GBM - 1) / GBM) * GBM)   // 100032

// ---------------- device scratch (static; no allocations) ----------------
__device__ float g_h1[(size_t)NROUND * H1C];    // layer1 linear output (padded rows)
__device__ float g_hrelu[(size_t)NN * H1C];     // layer1 GAT output after bias+relu
__device__ float g_h2[(size_t)NN * OUTC];       // layer2 linear output
__device__ float g_a1s[(size_t)NN * NH1];
__device__ float g_a1d[(size_t)NN * NH1];
__device__ float g_a2s[NN];
__device__ float g_a2d[NN];
__device__ int   g_cnt[NN];
__device__ int   g_rp[NN + 1];
__device__ int   g_cur[NN];
__device__ int   g_col[ETOT];
__device__ int   g_bsum[NB_SCAN + 1];
__device__ __nv_bfloat16 g_whi[FIN * GBN];
__device__ __nv_bfloat16 g_wlo[FIN * GBN];

// ---------------- cp.async helpers ----------------
__device__ __forceinline__ void cp16(void* smem, const void* gmem) {
    unsigned s = (unsigned)__cvta_generic_to_shared(smem);
    asm volatile("cp.async.cg.shared.global [%0], [%1], 16;\n" :: "r"(s), "l"(gmem));
}
#define CP_COMMIT() asm volatile("cp.async.commit_group;\n" ::: "memory")
#define CP_WAIT1()  asm volatile("cp.async.wait_group 1;\n" ::: "memory")
#define CP_WAIT0()  asm volatile("cp.async.wait_group 0;\n" ::: "memory")

// ---------------- CSR build ----------------
__global__ void k_zero_cnt() {
    int i = blockIdx.x * blockDim.x + threadIdx.x;
    if (i < NN) g_cnt[i] = 0;
}

__global__ void k_hist(const int* __restrict__ ei) {
    int i = blockIdx.x * blockDim.x + threadIdx.x;
    if (i < EE) {
        int d = ei[EE + i];
        if (d >= 0 && d < NN) atomicAdd(&g_cnt[d], 1);
    }
}

// split W into bf16 hi/lo once
__global__ void k_prepW(const float* __restrict__ W) {
    int i = blockIdx.x * blockDim.x + threadIdx.x;
    if (i < FIN * GBN) {
        float v = W[i];
        __nv_bfloat16 hi = __float2bfloat16_rn(v);
        g_whi[i] = hi;
        g_wlo[i] = __float2bfloat16_rn(v - __bfloat162float(hi));
    }
}

// exclusive scan of (cnt[i]+1) — the +1 accounts for the self loop of each node
__global__ void k_scan_block() {
    int i = blockIdx.x * SCAN_B + threadIdx.x;
    int v = (i < NN) ? (g_cnt[i] + 1) : 0;
    int lane = threadIdx.x & 31, wid = threadIdx.x >> 5;
    int s = v;
    #pragma unroll
    for (int o = 1; o < 32; o <<= 1) {
        int t = __shfl_up_sync(0xFFFFFFFFu, s, o);
        if (lane >= o) s += t;
    }
    __shared__ int wsum[32];
    if (lane == 31) wsum[wid] = s;
    __syncthreads();
    if (wid == 0) {
        int ws = wsum[lane];
        #pragma unroll
        for (int o = 1; o < 32; o <<= 1) {
            int t = __shfl_up_sync(0xFFFFFFFFu, ws, o);
            if (lane >= o) ws += t;
        }
        wsum[lane] = ws;
    }
    __syncthreads();
    int excl = s - v + (wid > 0 ? wsum[wid - 1] : 0);
    if (i < NN) g_rp[i] = excl;
    if (threadIdx.x == SCAN_B - 1) g_bsum[blockIdx.x] = wsum[31];
}

// parallel exclusive scan of the 98 block sums
__global__ void k_scan_sums() {
    int t = threadIdx.x;             // 0..127
    int lane = t & 31, wid = t >> 5;
    int v = (t < NB_SCAN) ? g_bsum[t] : 0;
    int s = v;
    #pragma unroll
    for (int o = 1; o < 32; o <<= 1) {
        int u = __shfl_up_sync(0xFFFFFFFFu, s, o);
        if (lane >= o) s += u;
    }
    __shared__ int wsum[4];
    if (lane == 31) wsum[wid] = s;
    __syncthreads();
    int add = 0;
    for (int wmm = 0; wmm < wid; wmm++) add += wsum[wmm];
    if (t < NB_SCAN) g_bsum[t] = s - v + add;   // exclusive
}

__global__ void k_add_offsets() {
    int i = blockIdx.x * SCAN_B + threadIdx.x;
    if (i < NN) {
        int r = g_rp[i] + g_bsum[i >> 10];
        g_rp[i] = r;
        g_cur[i] = r;
    }
    if (i == 0) g_rp[NN] = ETOT;
}

__global__ void k_scatter(const int* __restrict__ ei) {
    int i = blockIdx.x * blockDim.x + threadIdx.x;
    if (i >= ETOT) return;
    int s, d;
    if (i < EE) {
        s = ei[i];
        d = ei[EE + i];
    } else {
        s = d = i - EE;
    }
    if (s < 0 || s >= NN || d < 0 || d >= NN) return;
    int pos = atomicAdd(&g_cur[d], 1);
    g_col[pos] = s;
}

// ---------------- GEMM1: h1 = x @ W1 (bf16 split, cp.async) + fused attn dots ----------------
__device__ __forceinline__ unsigned pack_bf2(__nv_bfloat16 a, __nv_bfloat16 b) {
    __nv_bfloat162 t = __halves2bfloat162(a, b);
    return *(unsigned*)&t;
}

__global__ __launch_bounds__(128, 4) void k_gemm1(const float* __restrict__ x,
                                                  const float* __restrict__ att_s,
                                                  const float* __restrict__ att_d) {
    __shared__ float stA[2][GBM][GBK];                         // fp32 staging (2x8KB)
    __shared__ __nv_bfloat16 sAhi[GBM][A_LD];                  // 5.1KB
    __shared__ __nv_bfloat16 sAlo[GBM][A_LD];                  // 5.1KB
    __shared__ __nv_bfloat16 sBhi[2][GBK][B_LD];               // 9.2KB
    __shared__ __nv_bfloat16 sBlo[2][GBK][B_LD];               // 9.2KB

    int bm = blockIdx.x * GBM;
    int tid = threadIdx.x;
    int w = tid >> 5;
    int wm = w >> 1;       // 2 warps along M (32 rows each)
    int wn = w & 1;        // 2 warps along N (32 cols each)

    auto copyA = [&](int buf, int kt) {
        #pragma unroll
        for (int i = 0; i < 4; i++) {
            int c = tid + i * 128;
            int row = c >> 3;
            int off = (c & 7) * 4;            // float offset
            int grow = bm + row;
            if (grow < NN)
                cp16(&stA[buf][row][off], x + (size_t)grow * FIN + kt + off);
            else
                *(float4*)&stA[buf][row][off] = make_float4(0.f, 0.f, 0.f, 0.f);
        }
    };
    auto copyB = [&](int buf, int kt) {
        #pragma unroll
        for (int i = 0; i < 4; i++) {
            int c = tid + i * 128;            // 0..511
            int half = c >> 8;                // 0: hi, 1: lo
            int cc = c & 255;
            int row = cc >> 3;                // 0..31
            int off = (cc & 7) * 8;           // bf16 offset (8 bf16 = 16B)
            const __nv_bfloat16* src = (half ? g_wlo : g_whi) + (size_t)(kt + row) * GBN + off;
            __nv_bfloat16* dst = half ? &sBlo[buf][row][off] : &sBhi[buf][row][off];
            cp16(dst, src);
        }
    };
    auto convertA = [&](int buf) {
        #pragma unroll
        for (int i = 0; i < 4; i++) {
            int c = tid + i * 128;
            int row = c >> 3;
            int off = (c & 7) * 4;
            float4 v = *(float4*)&stA[buf][row][off];
            float vv[4] = {v.x, v.y, v.z, v.w};
            __nv_bfloat16 hi[4], lo[4];
            #pragma unroll
            for (int j = 0; j < 4; j++) {
                hi[j] = __float2bfloat16_rn(vv[j]);
                lo[j] = __float2bfloat16_rn(vv[j] - __bfloat162float(hi[j]));
            }
            *(uint2*)&sAhi[row][off] = make_uint2(pack_bf2(hi[0], hi[1]), pack_bf2(hi[2], hi[3]));
            *(uint2*)&sAlo[row][off] = make_uint2(pack_bf2(lo[0], lo[1]), pack_bf2(lo[2], lo[3]));
        }
    };

    wmma::fragment<wmma::accumulator, 16, 16, 16, float> acc[2][2];
    #pragma unroll
    for (int mi = 0; mi < 2; mi++)
        #pragma unroll
        for (int ni = 0; ni < 2; ni++) wmma::fill_fragment(acc[mi][ni], 0.0f);

    copyA(0, 0);        copyB(0, 0);        CP_COMMIT();
    copyA(1, GBK);      copyB(1, GBK);      CP_COMMIT();

    int cur = 0;
    for (int t = 0; t < NTILE; t++) {
        // last tile has no group committed behind it: drain fully (R12 bug fix)
        if (t == NTILE - 1) { CP_WAIT0(); } else { CP_WAIT1(); }
        __syncthreads();
        convertA(cur);
        __syncthreads();

        #pragma unroll
        for (int ks = 0; ks < GBK; ks += 16) {
            wmma::fragment<wmma::matrix_a, 16, 16, 16, __nv_bfloat16, wmma::row_major> ahi[2], alo[2];
            wmma::fragment<wmma::matrix_b, 16, 16, 16, __nv_bfloat16, wmma::row_major> bhi[2], blo[2];
            #pragma unroll
            for (int mi = 0; mi < 2; mi++) {
                wmma::load_matrix_sync(ahi[mi], &sAhi[wm * 32 + mi * 16][ks], A_LD);
                wmma::load_matrix_sync(alo[mi], &sAlo[wm * 32 + mi * 16][ks], A_LD);
            }
            #pragma unroll
            for (int ni = 0; ni < 2; ni++) {
                wmma::load_matrix_sync(bhi[ni], &sBhi[cur][ks][wn * 32 + ni * 16], B_LD);
                wmma::load_matrix_sync(blo[ni], &sBlo[cur][ks][wn * 32 + ni * 16], B_LD);
            }
            #pragma unroll
            for (int mi = 0; mi < 2; mi++)
                #pragma unroll
                for (int ni = 0; ni < 2; ni++) {
                    wmma::mma_sync(acc[mi][ni], ahi[mi], bhi[ni], acc[mi][ni]);
                    wmma::mma_sync(acc[mi][ni], ahi[mi], blo[ni], acc[mi][ni]);
                    wmma::mma_sync(acc[mi][ni], alo[mi], bhi[ni], acc[mi][ni]);
                }
        }
        __syncthreads();            // stA[cur]/sB[cur] fully consumed

        if (t + 2 < NTILE) {
            copyA(cur, (t + 2) * GBK);
            copyB(cur, (t + 2) * GBK);
            CP_COMMIT();
        }
        cur ^= 1;
    }

    // epilogue: g_h1 rows padded to NROUND — no bounds checks
    #pragma unroll
    for (int mi = 0; mi < 2; mi++)
        #pragma unroll
        for (int ni = 0; ni < 2; ni++) {
            int row = bm + wm * 32 + mi * 16;
            int col = wn * 32 + ni * 16;
            wmma::store_matrix_sync(g_h1 + (size_t)row * H1C + col, acc[mi][ni],
                                    H1C, wmma::mem_row_major);
        }

    // fused attention dots: block's 64 h1 rows are L1-hot; __syncthreads gives
    // block-scope visibility of our own global stores.
    __syncthreads();
    {
        int row = tid & 63;          // 0..63
        int half = tid >> 6;         // 0: src dots, 1: dst dots
        int grow = bm + row;
        if (grow < NN) {
            const float* av = half ? att_d : att_s;
            const float* hrow = g_h1 + (size_t)grow * H1C;
            float a[NH1];
            #pragma unroll
            for (int hh = 0; hh < NH1; hh++) a[hh] = 0.f;
            #pragma unroll
            for (int i = 0; i < H1C; i++)
                a[i >> 3] = fmaf(hrow[i], __ldg(av + i), a[i >> 3]);
            float* dst = (half ? g_a1d : g_a1s) + (size_t)grow * NH1;
            #pragma unroll
            for (int hh = 0; hh < NH1; hh++) dst[hh] = a[hh];
        }
    }
}

__device__ __forceinline__ float lrelu(float e) {
    return e > 0.f ? e : NEG_SLOPE * e;
}

// ---------------- layer-1 aggregation: warp per destination, single pass, ILP-2 ----------------
__global__ __launch_bounds__(256) void k_agg1(const float* __restrict__ b1) {
    int warp = (blockIdx.x * blockDim.x + threadIdx.x) >> 5;
    int lane = threadIdx.x & 31;
    if (warp >= NN) return;
    int d = warp;
    int hA = lane >> 3;
    int hB = 4 + (lane >> 3);
    float aDA = g_a1d[(size_t)d * NH1 + hA];
    float aDB = g_a1d[(size_t)d * NH1 + hB];
    int beg = g_rp[d], end = g_rp[d + 1];

    float denA = 0.f, denB = 0.f, acc0 = 0.f, acc1 = 0.f;
    int k = beg;
    for (; k + 1 < end; k += 2) {
        int s0 = g_col[k], s1 = g_col[k + 1];
        float e0A = g_a1s[(size_t)s0 * NH1 + hA];
        float e0B = g_a1s[(size_t)s0 * NH1 + hB];
        float e1A = g_a1s[(size_t)s1 * NH1 + hA];
        float e1B = g_a1s[(size_t)s1 * NH1 + hB];
        const float* r0 = g_h1 + (size_t)s0 * H1C;
        const float* r1 = g_h1 + (size_t)s1 * H1C;
        float h00 = r0[lane], h01 = r0[lane + 32];
        float h10 = r1[lane], h11 = r1[lane + 32];
        float w0A = __expf(lrelu(e0A + aDA));
        float w0B = __expf(lrelu(e0B + aDB));
        float w1A = __expf(lrelu(e1A + aDA));
        float w1B = __expf(lrelu(e1B + aDB));
        denA += w0A + w1A;
        denB += w0B + w1B;
        acc0 = fmaf(w0A, h00, acc0); acc0 = fmaf(w1A, h10, acc0);
        acc1 = fmaf(w0B, h01, acc1); acc1 = fmaf(w1B, h11, acc1);
    }
    if (k < end) {
        int s = g_col[k];
        float wA = __expf(lrelu(g_a1s[(size_t)s * NH1 + hA] + aDA));
        float wB = __expf(lrelu(g_a1s[(size_t)s * NH1 + hB] + aDB));
        denA += wA; denB += wB;
        const float* hrow = g_h1 + (size_t)s * H1C;
        acc0 = fmaf(wA, hrow[lane], acc0);
        acc1 = fmaf(wB, hrow[lane + 32], acc1);
    }
    float o0 = acc0 / (denA + EPS_F) + __ldg(b1 + lane);
    float o1 = acc1 / (denB + EPS_F) + __ldg(b1 + lane + 32);
    o0 = fmaxf(o0, 0.f);
    o1 = fmaxf(o1, 0.f);
    g_hrelu[(size_t)d * H1C + lane] = o0;
    g_hrelu[(size_t)d * H1C + lane + 32] = o1;
}

// ---------------- GEMM2 + layer-2 attention dots: thread per node ----------------
__global__ __launch_bounds__(256) void k_gemm2(const float* __restrict__ W2,
                                               const float* __restrict__ att_s2,
                                               const float* __restrict__ att_d2) {
    __shared__ float Ws[H1C * OUTC];
    __shared__ float s_as[OUTC], s_ad[OUTC];
    for (int i = threadIdx.x; i < H1C * OUTC; i += blockDim.x) Ws[i] = W2[i];
    for (int i = threadIdx.x; i < OUTC; i += blockDim.x) {
        s_as[i] = att_s2[i];
        s_ad[i] = att_d2[i];
    }
    __syncthreads();
    int n = blockIdx.x * blockDim.x + threadIdx.x;
    if (n >= NN) return;
    const float* xr = g_hrelu + (size_t)n * H1C;
    float acc[OUTC];
    #pragma unroll
    for (int c = 0; c < OUTC; c++) acc[c] = 0.f;
    #pragma unroll 4
    for (int k = 0; k < H1C; k++) {
        float xv = xr[k];
        #pragma unroll
        for (int c = 0; c < OUTC; c++)
            acc[c] = fmaf(xv, Ws[k * OUTC + c], acc[c]);
    }
    float as = 0.f, ad = 0.f;
    float* out = g_h2 + (size_t)n * OUTC;
    #pragma unroll
    for (int c = 0; c < OUTC; c++) {
        out[c] = acc[c];
        as = fmaf(acc[c], s_as[c], as);
        ad = fmaf(acc[c], s_ad[c], ad);
    }
    g_a2s[n] = as;
    g_a2d[n] = ad;
}

// ---------------- layer-2 aggregation + bias + log_softmax: warp per dst, ILP-2 ----------------
__global__ __launch_bounds__(256) void k_agg2(const float* __restrict__ b2,
                                              float* __restrict__ out) {
    int warp = (blockIdx.x * blockDim.x + threadIdx.x) >> 5;
    int lane = threadIdx.x & 31;
    if (warp >= NN) return;
    int d = warp;
    float aD = g_a2d[d];
    int beg = g_rp[d], end = g_rp[d + 1];

    float den = 0.f, acc0 = 0.f, acc1 = 0.f;
    int k = beg;
    for (; k + 1 < end; k += 2) {
        int s0 = g_col[k], s1 = g_col[k + 1];
        float e0 = g_a2s[s0], e1 = g_a2s[s1];
        const float* r0 = g_h2 + (size_t)s0 * OUTC;
        const float* r1 = g_h2 + (size_t)s1 * OUTC;
        float h00 = r0[lane], h10 = r1[lane];
        float h01 = 0.f, h11 = 0.f;
        if (lane < 8) { h01 = r0[32 + lane]; h11 = r1[32 + lane]; }
        float w0 = __expf(lrelu(e0 + aD));
        float w1 = __expf(lrelu(e1 + aD));
        den += w0 + w1;
        acc0 = fmaf(w0, h00, acc0); acc0 = fmaf(w1, h10, acc0);
        acc1 = fmaf(w0, h01, acc1); acc1 = fmaf(w1, h11, acc1);
    }
    if (k < end) {
        int s = g_col[k];
        float wv = __expf(lrelu(g_a2s[s] + aD));
        den += wv;
        const float* hrow = g_h2 + (size_t)s * OUTC;
        acc0 = fmaf(wv, hrow[lane], acc0);
        if (lane < 8) acc1 = fmaf(wv, hrow[32 + lane], acc1);
    }
    float inv = 1.f / (den + EPS_F);
    float v0 = acc0 * inv + __ldg(b2 + lane);
    float v1 = (lane < 8) ? (acc1 * inv + __ldg(b2 + 32 + lane)) : -INFINITY;

    float mx = fmaxf(v0, v1);
    #pragma unroll
    for (int o = 16; o > 0; o >>= 1)
        mx = fmaxf(mx, __shfl_xor_sync(0xFFFFFFFFu, mx, o));
    float se = __expf(v0 - mx) + ((lane < 8) ? __expf(v1 - mx) : 0.f);
    #pragma unroll
    for (int o = 16; o > 0; o >>= 1)
        se += __shfl_xor_sync(0xFFFFFFFFu, se, o);
    float lse = logf(se);
    float* orow = out + (size_t)d * OUTC;
    orow[lane] = v0 - mx - lse;
    if (lane < 8) orow[32 + lane] = v1 - mx - lse;
}

// ---------------- launcher ----------------
extern "C" void kernel_launch(void* const* d_in, const int* in_sizes, int n_in,
                              void* d_out, int out_size) {
    const float* x    = (const float*)d_in[0];
    const int*   ei   = (const int*)d_in[1];     // int32 (JAX x64 disabled)
    const float* W1   = (const float*)d_in[2];
    const float* as1  = (const float*)d_in[3];
    const float* ad1  = (const float*)d_in[4];
    const float* b1   = (const float*)d_in[5];
    const float* W2   = (const float*)d_in[6];
    const float* as2  = (const float*)d_in[7];
    const float* ad2  = (const float*)d_in[8];
    const float* b2   = (const float*)d_in[9];
    float*       out  = (float*)d_out;

    // allow gemm1's 44.7KB static smem to coexist with more CTAs/SM
    static bool carveout_set = false;
    if (!carveout_set) {
        cudaFuncSetAttribute(k_gemm1, cudaFuncAttributePreferredSharedMemoryCarveout, 100);
        carveout_set = true;
    }

    // gemm1 kept at launch index 3 — ncu's capture slot
    k_zero_cnt<<<(NN + 255) / 256, 256>>>();                 // 0
    k_hist<<<(EE + 255) / 256, 256>>>(ei);                   // 1
    k_prepW<<<(FIN * GBN + 255) / 256, 256>>>(W1);           // 2
    k_gemm1<<<NROUND / GBM, 128>>>(x, as1, ad1);             // 3  <- profiled (+fused dots)
    k_scan_block<<<NB_SCAN, SCAN_B>>>();                     // 4
    k_scan_sums<<<1, 128>>>();                               // 5
    k_add_offsets<<<NB_SCAN, SCAN_B>>>();                    // 6
    k_scatter<<<(ETOT + 255) / 256, 256>>>(ei);              // 7

    // layer 1
    k_agg1<<<(NN * 32 + 255) / 256, 256>>>(b1);              // 8

    // layer 2 + log_softmax
    k_gemm2<<<(NN + 255) / 256, 256>>>(W2, as2, ad2);        // 9
    k_agg2<<<(NN * 32 + 255) / 256, 256>>>(b2, out);         // 10
}

// round 17
// speedup vs baseline: 1.7272x; 1.7272x over previous
#include <cuda_runtime.h>
#include <cuda_bf16.h>
#include <mma.h>
#include <math.h>

using namespace nvcuda;

// Problem constants (fixed dataset)
#define NN      100000          // nodes
#define EE      1600000         // edges (without self loops)
#define ETOT    (EE + NN)       // with self loops
#define FIN     512
#define H1C     64              // 8 heads * 8 channels
#define NH1     8
#define OUTC    40
#define NEG_SLOPE 0.2f
#define EPS_F   1e-16f

#define SCAN_B  1024
#define NB_SCAN ((NN + SCAN_B - 1) / SCAN_B)   // 98

// GEMM1 tiling (64x64x32, 128 threads, cp.async pipelined) — R13 known-good
#define GBM 64
#define GBK 32
#define GBN 64
#define NTILE (FIN / GBK)                       // 16
#define A_LD 40
#define B_LD 72
#define NROUND (((NN + GBM - 1) / GBM) * GBM)   // 100032

// ---------------- device scratch (static; no allocations) ----------------
__device__ float g_h1[(size_t)NROUND * H1C];
__device__ float g_hrelu[(size_t)NN * H1C];
__device__ float g_h2[(size_t)NN * OUTC];
__device__ float g_a1s[(size_t)NN * NH1];
__device__ float g_a1d[(size_t)NN * NH1];
__device__ float g_a2s[NN];
__device__ float g_a2d[NN];
__device__ int   g_cnt[NN];
__device__ int   g_rp[NN + 1];
__device__ int   g_cur[NN];
__device__ int   g_col[ETOT];
__device__ int   g_bsum[NB_SCAN + 1];
__device__ __nv_bfloat16 g_whi[FIN * GBN];
__device__ __nv_bfloat16 g_wlo[FIN * GBN];

// ---------------- cp.async helpers ----------------
__device__ __forceinline__ void cp16(void* smem, const void* gmem) {
    unsigned s = (unsigned)__cvta_generic_to_shared(smem);
    asm volatile("cp.async.cg.shared.global [%0], [%1], 16;\n" :: "r"(s), "l"(gmem));
}
#define CP_COMMIT() asm volatile("cp.async.commit_group;\n" ::: "memory")
#define CP_WAIT1()  asm volatile("cp.async.wait_group 1;\n" ::: "memory")
#define CP_WAIT0()  asm volatile("cp.async.wait_group 0;\n" ::: "memory")

// ---------------- CSR build ----------------
__global__ void k_zero_cnt() {
    int i = blockIdx.x * blockDim.x + threadIdx.x;
    if (i < NN) g_cnt[i] = 0;
}

__global__ void k_hist(const int* __restrict__ ei) {
    int i = blockIdx.x * blockDim.x + threadIdx.x;
    if (i < EE) {
        int d = ei[EE + i];
        if (d >= 0 && d < NN) atomicAdd(&g_cnt[d], 1);
    }
}

// split W into bf16 hi/lo once
__global__ void k_prepW(const float* __restrict__ W) {
    int i = blockIdx.x * blockDim.x + threadIdx.x;
    if (i < FIN * GBN) {
        float v = W[i];
        __nv_bfloat16 hi = __float2bfloat16_rn(v);
        g_whi[i] = hi;
        g_wlo[i] = __float2bfloat16_rn(v - __bfloat162float(hi));
    }
}

// exclusive scan of (cnt[i]+1) — +1 is the self loop
__global__ void k_scan_block() {
    int i = blockIdx.x * SCAN_B + threadIdx.x;
    int v = (i < NN) ? (g_cnt[i] + 1) : 0;
    int lane = threadIdx.x & 31, wid = threadIdx.x >> 5;
    int s = v;
    #pragma unroll
    for (int o = 1; o < 32; o <<= 1) {
        int t = __shfl_up_sync(0xFFFFFFFFu, s, o);
        if (lane >= o) s += t;
    }
    __shared__ int wsum[32];
    if (lane == 31) wsum[wid] = s;
    __syncthreads();
    if (wid == 0) {
        int ws = wsum[lane];
        #pragma unroll
        for (int o = 1; o < 32; o <<= 1) {
            int t = __shfl_up_sync(0xFFFFFFFFu, ws, o);
            if (lane >= o) ws += t;
        }
        wsum[lane] = ws;
    }
    __syncthreads();
    int excl = s - v + (wid > 0 ? wsum[wid - 1] : 0);
    if (i < NN) g_rp[i] = excl;
    if (threadIdx.x == SCAN_B - 1) g_bsum[blockIdx.x] = wsum[31];
}

__global__ void k_scan_sums() {
    int t = threadIdx.x;             // 0..127
    int lane = t & 31, wid = t >> 5;
    int v = (t < NB_SCAN) ? g_bsum[t] : 0;
    int s = v;
    #pragma unroll
    for (int o = 1; o < 32; o <<= 1) {
        int u = __shfl_up_sync(0xFFFFFFFFu, s, o);
        if (lane >= o) s += u;
    }
    __shared__ int wsum[4];
    if (lane == 31) wsum[wid] = s;
    __syncthreads();
    int add = 0;
    for (int wmm = 0; wmm < wid; wmm++) add += wsum[wmm];
    if (t < NB_SCAN) g_bsum[t] = s - v + add;   // exclusive
}

__global__ void k_add_offsets() {
    int i = blockIdx.x * SCAN_B + threadIdx.x;
    if (i < NN) {
        int r = g_rp[i] + g_bsum[i >> 10];
        g_rp[i] = r;
        g_cur[i] = r;
    }
    if (i == 0) g_rp[NN] = ETOT;
}

__global__ void k_scatter(const int* __restrict__ ei) {
    int i = blockIdx.x * blockDim.x + threadIdx.x;
    if (i >= ETOT) return;
    int s, d;
    if (i < EE) {
        s = ei[i];
        d = ei[EE + i];
    } else {
        s = d = i - EE;
    }
    if (s < 0 || s >= NN || d < 0 || d >= NN) return;
    int pos = atomicAdd(&g_cur[d], 1);
    g_col[pos] = s;
}

// ---------------- GEMM1: h1 = x @ W1, bf16 split, cp.async (R13 exact) ----------------
__device__ __forceinline__ unsigned pack_bf2(__nv_bfloat16 a, __nv_bfloat16 b) {
    __nv_bfloat162 t = __halves2bfloat162(a, b);
    return *(unsigned*)&t;
}

__global__ __launch_bounds__(128) void k_gemm1(const float* __restrict__ x) {
    __shared__ float stA[2][GBM][GBK];
    __shared__ __nv_bfloat16 sAhi[GBM][A_LD];
    __shared__ __nv_bfloat16 sAlo[GBM][A_LD];
    __shared__ __nv_bfloat16 sBhi[2][GBK][B_LD];
    __shared__ __nv_bfloat16 sBlo[2][GBK][B_LD];

    int bm = blockIdx.x * GBM;
    int tid = threadIdx.x;
    int w = tid >> 5;
    int wm = w >> 1;
    int wn = w & 1;

    auto copyA = [&](int buf, int kt) {
        #pragma unroll
        for (int i = 0; i < 4; i++) {
            int c = tid + i * 128;
            int row = c >> 3;
            int off = (c & 7) * 4;
            int grow = bm + row;
            if (grow < NN)
                cp16(&stA[buf][row][off], x + (size_t)grow * FIN + kt + off);
            else
                *(float4*)&stA[buf][row][off] = make_float4(0.f, 0.f, 0.f, 0.f);
        }
    };
    auto copyB = [&](int buf, int kt) {
        #pragma unroll
        for (int i = 0; i < 4; i++) {
            int c = tid + i * 128;
            int half = c >> 8;
            int cc = c & 255;
            int row = cc >> 3;
            int off = (cc & 7) * 8;
            const __nv_bfloat16* src = (half ? g_wlo : g_whi) + (size_t)(kt + row) * GBN + off;
            __nv_bfloat16* dst = half ? &sBlo[buf][row][off] : &sBhi[buf][row][off];
            cp16(dst, src);
        }
    };
    auto convertA = [&](int buf) {
        #pragma unroll
        for (int i = 0; i < 4; i++) {
            int c = tid + i * 128;
            int row = c >> 3;
            int off = (c & 7) * 4;
            float4 v = *(float4*)&stA[buf][row][off];
            float vv[4] = {v.x, v.y, v.z, v.w};
            __nv_bfloat16 hi[4], lo[4];
            #pragma unroll
            for (int j = 0; j < 4; j++) {
                hi[j] = __float2bfloat16_rn(vv[j]);
                lo[j] = __float2bfloat16_rn(vv[j] - __bfloat162float(hi[j]));
            }
            *(uint2*)&sAhi[row][off] = make_uint2(pack_bf2(hi[0], hi[1]), pack_bf2(hi[2], hi[3]));
            *(uint2*)&sAlo[row][off] = make_uint2(pack_bf2(lo[0], lo[1]), pack_bf2(lo[2], lo[3]));
        }
    };

    wmma::fragment<wmma::accumulator, 16, 16, 16, float> acc[2][2];
    #pragma unroll
    for (int mi = 0; mi < 2; mi++)
        #pragma unroll
        for (int ni = 0; ni < 2; ni++) wmma::fill_fragment(acc[mi][ni], 0.0f);

    copyA(0, 0);        copyB(0, 0);        CP_COMMIT();
    copyA(1, GBK);      copyB(1, GBK);      CP_COMMIT();

    int cur = 0;
    for (int t = 0; t < NTILE; t++) {
        if (t == NTILE - 1) { CP_WAIT0(); } else { CP_WAIT1(); }
        __syncthreads();
        convertA(cur);
        __syncthreads();

        #pragma unroll
        for (int ks = 0; ks < GBK; ks += 16) {
            wmma::fragment<wmma::matrix_a, 16, 16, 16, __nv_bfloat16, wmma::row_major> ahi[2], alo[2];
            wmma::fragment<wmma::matrix_b, 16, 16, 16, __nv_bfloat16, wmma::row_major> bhi[2], blo[2];
            #pragma unroll
            for (int mi = 0; mi < 2; mi++) {
                wmma::load_matrix_sync(ahi[mi], &sAhi[wm * 32 + mi * 16][ks], A_LD);
                wmma::load_matrix_sync(alo[mi], &sAlo[wm * 32 + mi * 16][ks], A_LD);
            }
            #pragma unroll
            for (int ni = 0; ni < 2; ni++) {
                wmma::load_matrix_sync(bhi[ni], &sBhi[cur][ks][wn * 32 + ni * 16], B_LD);
                wmma::load_matrix_sync(blo[ni], &sBlo[cur][ks][wn * 32 + ni * 16], B_LD);
            }
            #pragma unroll
            for (int mi = 0; mi < 2; mi++)
                #pragma unroll
                for (int ni = 0; ni < 2; ni++) {
                    wmma::mma_sync(acc[mi][ni], ahi[mi], bhi[ni], acc[mi][ni]);
                    wmma::mma_sync(acc[mi][ni], ahi[mi], blo[ni], acc[mi][ni]);
                    wmma::mma_sync(acc[mi][ni], alo[mi], bhi[ni], acc[mi][ni]);
                }
        }
        __syncthreads();

        if (t + 2 < NTILE) {
            copyA(cur, (t + 2) * GBK);
            copyB(cur, (t + 2) * GBK);
            CP_COMMIT();
        }
        cur ^= 1;
    }

    #pragma unroll
    for (int mi = 0; mi < 2; mi++)
        #pragma unroll
        for (int ni = 0; ni < 2; ni++) {
            int row = bm + wm * 32 + mi * 16;
            int col = wn * 32 + ni * 16;
            wmma::store_matrix_sync(g_h1 + (size_t)row * H1C + col, acc[mi][ni],
                                    H1C, wmma::mem_row_major);
        }
}

// ---------------- attention dot products layer 1 (separate, coalesced-enough) ----------------
__global__ void k_dots1(const float* __restrict__ att_s, const float* __restrict__ att_d) {
    int n = blockIdx.x * blockDim.x + threadIdx.x;
    if (n >= NN) return;
    const float* h = g_h1 + (size_t)n * H1C;
    float as[NH1], ad[NH1];
    #pragma unroll
    for (int hh = 0; hh < NH1; hh++) { as[hh] = 0.f; ad[hh] = 0.f; }
    #pragma unroll
    for (int i = 0; i < H1C; i++) {
        float hv = h[i];
        int hh = i >> 3;
        as[hh] = fmaf(hv, __ldg(att_s + i), as[hh]);
        ad[hh] = fmaf(hv, __ldg(att_d + i), ad[hh]);
    }
    #pragma unroll
    for (int hh = 0; hh < NH1; hh++) {
        g_a1s[(size_t)n * NH1 + hh] = as[hh];
        g_a1d[(size_t)n * NH1 + hh] = ad[hh];
    }
}

__device__ __forceinline__ float lrelu(float e) {
    return e > 0.f ? e : NEG_SLOPE * e;
}

// ---------------- layer-1 aggregation: warp/dst; lane handles col pair {2l,2l+1} ----------------
// Pair lies inside one head (head width 8) -> ONE exp + ONE 64-bit load per edge per lane.
__global__ __launch_bounds__(256) void k_agg1(const float* __restrict__ b1) {
    int warp = (blockIdx.x * blockDim.x + threadIdx.x) >> 5;
    int lane = threadIdx.x & 31;
    if (warp >= NN) return;
    int d = warp;
    int col = lane * 2;            // 0,2,...,62
    int hh  = lane >> 2;           // head of this col pair (8 cols/head)
    float aD = g_a1d[(size_t)d * NH1 + hh];
    int beg = g_rp[d], end = g_rp[d + 1];

    float den = 0.f;
    float accx = 0.f, accy = 0.f;
    int k = beg;
    for (; k + 1 < end; k += 2) {
        int s0 = g_col[k], s1 = g_col[k + 1];
        float e0 = g_a1s[(size_t)s0 * NH1 + hh];
        float e1 = g_a1s[(size_t)s1 * NH1 + hh];
        float2 h0 = *(const float2*)(g_h1 + (size_t)s0 * H1C + col);
        float2 h1 = *(const float2*)(g_h1 + (size_t)s1 * H1C + col);
        float w0 = __expf(lrelu(e0 + aD));
        float w1 = __expf(lrelu(e1 + aD));
        den += w0 + w1;
        accx = fmaf(w0, h0.x, accx); accx = fmaf(w1, h1.x, accx);
        accy = fmaf(w0, h0.y, accy); accy = fmaf(w1, h1.y, accy);
    }
    if (k < end) {
        int s = g_col[k];
        float w = __expf(lrelu(g_a1s[(size_t)s * NH1 + hh] + aD));
        float2 h = *(const float2*)(g_h1 + (size_t)s * H1C + col);
        den += w;
        accx = fmaf(w, h.x, accx);
        accy = fmaf(w, h.y, accy);
    }
    float inv = 1.f / (den + EPS_F);
    float o0 = fmaxf(accx * inv + __ldg(b1 + col), 0.f);
    float o1 = fmaxf(accy * inv + __ldg(b1 + col + 1), 0.f);
    *(float2*)(g_hrelu + (size_t)d * H1C + col) = make_float2(o0, o1);
}

// ---------------- GEMM2 + layer-2 attention dots: thread per node ----------------
__global__ __launch_bounds__(256) void k_gemm2(const float* __restrict__ W2,
                                               const float* __restrict__ att_s2,
                                               const float* __restrict__ att_d2) {
    __shared__ float Ws[H1C * OUTC];
    __shared__ float s_as[OUTC], s_ad[OUTC];
    for (int i = threadIdx.x; i < H1C * OUTC; i += blockDim.x) Ws[i] = W2[i];
    for (int i = threadIdx.x; i < OUTC; i += blockDim.x) {
        s_as[i] = att_s2[i];
        s_ad[i] = att_d2[i];
    }
    __syncthreads();
    int n = blockIdx.x * blockDim.x + threadIdx.x;
    if (n >= NN) return;
    const float* xr = g_hrelu + (size_t)n * H1C;
    float acc[OUTC];
    #pragma unroll
    for (int c = 0; c < OUTC; c++) acc[c] = 0.f;
    #pragma unroll 4
    for (int k = 0; k < H1C; k++) {
        float xv = xr[k];
        #pragma unroll
        for (int c = 0; c < OUTC; c++)
            acc[c] = fmaf(xv, Ws[k * OUTC + c], acc[c]);
    }
    float as = 0.f, ad = 0.f;
    float* out = g_h2 + (size_t)n * OUTC;
    #pragma unroll
    for (int c = 0; c < OUTC; c++) {
        out[c] = acc[c];
        as = fmaf(acc[c], s_as[c], as);
        ad = fmaf(acc[c], s_ad[c], ad);
    }
    g_a2s[n] = as;
    g_a2d[n] = ad;
}

// ---------------- layer-2 aggregation + log_softmax: warp/dst; lane<20 holds col pair ----------------
__global__ __launch_bounds__(256) void k_agg2(const float* __restrict__ b2,
                                              float* __restrict__ out) {
    int warp = (blockIdx.x * blockDim.x + threadIdx.x) >> 5;
    int lane = threadIdx.x & 31;
    if (warp >= NN) return;
    int d = warp;
    int col = lane * 2;            // lane<20 covers cols 0..39
    bool active = lane < 20;
    float aD = g_a2d[d];
    int beg = g_rp[d], end = g_rp[d + 1];

    float den = 0.f, accx = 0.f, accy = 0.f;
    int k = beg;
    for (; k + 1 < end; k += 2) {
        int s0 = g_col[k], s1 = g_col[k + 1];
        float e0 = g_a2s[s0], e1 = g_a2s[s1];
        float2 h0 = make_float2(0.f, 0.f), h1 = make_float2(0.f, 0.f);
        if (active) {
            h0 = *(const float2*)(g_h2 + (size_t)s0 * OUTC + col);
            h1 = *(const float2*)(g_h2 + (size_t)s1 * OUTC + col);
        }
        float w0 = __expf(lrelu(e0 + aD));
        float w1 = __expf(lrelu(e1 + aD));
        den += w0 + w1;
        accx = fmaf(w0, h0.x, accx); accx = fmaf(w1, h1.x, accx);
        accy = fmaf(w0, h0.y, accy); accy = fmaf(w1, h1.y, accy);
    }
    if (k < end) {
        int s = g_col[k];
        float w = __expf(lrelu(g_a2s[s] + aD));
        den += w;
        if (active) {
            float2 h = *(const float2*)(g_h2 + (size_t)s * OUTC + col);
            accx = fmaf(w, h.x, accx);
            accy = fmaf(w, h.y, accy);
        }
    }
    float inv = 1.f / (den + EPS_F);
    float v0 = active ? (accx * inv + __ldg(b2 + col))     : -INFINITY;
    float v1 = active ? (accy * inv + __ldg(b2 + col + 1)) : -INFINITY;

    // log_softmax over 40 values held as pairs in lanes 0..19
    float mx = fmaxf(v0, v1);
    #pragma unroll
    for (int o = 16; o > 0; o >>= 1)
        mx = fmaxf(mx, __shfl_xor_sync(0xFFFFFFFFu, mx, o));
    float se = active ? (__expf(v0 - mx) + __expf(v1 - mx)) : 0.f;
    #pragma unroll
    for (int o = 16; o > 0; o >>= 1)
        se += __shfl_xor_sync(0xFFFFFFFFu, se, o);
    float lse = logf(se);
    if (active)
        *(float2*)(out + (size_t)d * OUTC + col) = make_float2(v0 - mx - lse, v1 - mx - lse);
}

// ---------------- launcher ----------------
extern "C" void kernel_launch(void* const* d_in, const int* in_sizes, int n_in,
                              void* d_out, int out_size) {
    const float* x    = (const float*)d_in[0];
    const int*   ei   = (const int*)d_in[1];     // int32 (JAX x64 disabled)
    const float* W1   = (const float*)d_in[2];
    const float* as1  = (const float*)d_in[3];
    const float* ad1  = (const float*)d_in[4];
    const float* b1   = (const float*)d_in[5];
    const float* W2   = (const float*)d_in[6];
    const float* as2  = (const float*)d_in[7];
    const float* ad2  = (const float*)d_in[8];
    const float* b2   = (const float*)d_in[9];
    float*       out  = (float*)d_out;

    // gemm1 kept at launch index 3 — ncu's capture slot
    k_zero_cnt<<<(NN + 255) / 256, 256>>>();                 // 0
    k_hist<<<(EE + 255) / 256, 256>>>(ei);                   // 1
    k_prepW<<<(FIN * GBN + 255) / 256, 256>>>(W1);           // 2
    k_gemm1<<<NROUND / GBM, 128>>>(x);                       // 3  <- profiled
    k_scan_block<<<NB_SCAN, SCAN_B>>>();                     // 4
    k_scan_sums<<<1, 128>>>();                               // 5
    k_add_offsets<<<NB_SCAN, SCAN_B>>>();                    // 6
    k_scatter<<<(ETOT + 255) / 256, 256>>>(ei);              // 7

    // layer 1
    k_dots1<<<(NN + 255) / 256, 256>>>(as1, ad1);            // 8
    k_agg1<<<(NN * 32 + 255) / 256, 256>>>(b1);              // 9

    // layer 2 + log_softmax
    k_gemm2<<<(NN + 255) / 256, 256>>>(W2, as2, ad2);        // 10
    k_agg2<<<(NN * 32 + 255) / 256, 256>>>(b2, out);         // 11
}